// round 16
// baseline (speedup 1.0000x reference)
#include <cuda_runtime.h>
#include <cuda_fp16.h>
#include <cstdint>

// Problem constants.
#define NB 8192
#define NH 1024
#define NO 256
#define NE 16

// GEMM tiling: CTA = 32(M) x 128(N), K slabs of 32 halfs, 4-stage pipeline.
#define BM 32
#define BN 128
#define BKS 32
#define NSLAB (NH / BKS)   // 32
#define THREADS 256
#define STAGES 4
#define A_STAGE_B 2048                  // 32 rows x 64 B (swizzled chunks)
#define B_STAGE_B 8192                  // 128 rows x 64 B (swizzled chunks)
#define A_OFF 0
#define B_OFF (STAGES * A_STAGE_B)      // 8192
#define BIAS_OFF (B_OFF + STAGES * B_STAGE_B)   // 40960
#define PRM_OFF (BIAS_OFF + BN * 4)             // 41472
#define MBAR_OFF (PRM_OFF + BM * 4)             // 41600  (4 full + 4 empty = 64 B)
#define SMEM_TOTAL (MBAR_OFF + 64)              // 41664

// --- scratch (no allocs allowed) ---
__device__ int    g_perm[NB];
__device__ int    g_off[NE + 1];
__device__ int    g_counts[NE];
__device__ __half W16t[NE * 2 * NSLAB * 128 * 32]; // W fp16 tiled [e][nt][slab][row][32], chunk-swizzled

// swizzle: 16B-chunk c (0..3) in row r -> c ^ ((r>>1)&3)
#define SWZ(r, c) ((c) ^ (((r) >> 1) & 3))

// ---------------- prep: W convert (2048 blocks) + bin (1 block) ----------------
__global__ __launch_bounds__(256)
void prep_kernel(const float* __restrict__ W,
                 const int* __restrict__ num, const int* __restrict__ c, int cmap_n) {
    const int b = blockIdx.x;
    const int t = threadIdx.x;
    if (b < 2048) {
        const int og = b * 2 + (t >> 7);            // global W row 0..4095
        const int e  = og >> 8;
        const int o  = og & 255;
        const int nt = o >> 7;
        const int r  = o & 127;
        const int h0 = (t & 127) * 8;               // k offset (8 floats)
        const int slab = h0 >> 5;
        const int cj = (h0 & 31) >> 3;              // 16B chunk 0..3
        const float* src = W + (size_t)og * NH + h0;
        float4 v0 = ((const float4*)src)[0];
        float4 v1 = ((const float4*)src)[1];
        __half2 h[4];
        h[0] = __floats2half2_rn(v0.x, v0.y);
        h[1] = __floats2half2_rn(v0.z, v0.w);
        h[2] = __floats2half2_rn(v1.x, v1.y);
        h[3] = __floats2half2_rn(v1.z, v1.w);
        __half* dst = W16t + ((((size_t)(e * 2 + nt) * NSLAB + slab) * 128 + r) * 32
                              + SWZ(r, cj) * 8);
        *(uint4*)dst = *(uint4*)h;
    } else {
        // bin: single block
        __shared__ int cs[1024];
        __shared__ int scnt[NE];
        __shared__ int scur[NE];
        for (int i = t; i < cmap_n && i < 1024; i += 256) cs[i] = c[i] & (NE - 1);
        if (t < NE) scnt[t] = 0;
        __syncthreads();
        int le[NB / 256];
        #pragma unroll
        for (int j = 0; j < NB / 256; j++) {
            int i = t + j * 256;
            int idx = num[i];
            idx = min(max(idx, 0), cmap_n - 1);
            le[j] = cs[idx];
            atomicAdd(&scnt[le[j]], 1);
        }
        __syncthreads();
        if (t == 0) {
            int acc = 0;
            g_off[0] = 0;
            #pragma unroll
            for (int e = 0; e < NE; e++) {
                scur[e] = acc;
                acc += scnt[e];
                g_off[e + 1] = acc;
                g_counts[e] = scnt[e];
            }
        }
        __syncthreads();
        #pragma unroll
        for (int j = 0; j < NB / 256; j++) {
            int pos = atomicAdd(&scur[le[j]], 1);
            g_perm[pos] = t + j * 256;
        }
    }
}

// ---------------- helpers ----------------
__device__ __forceinline__ uint32_t smem_u32(const void* p) {
    uint32_t a;
    asm("{ .reg .u64 t; cvta.to.shared.u64 t, %1; cvt.u32.u64 %0, t; }" : "=r"(a) : "l"(p));
    return a;
}

__device__ __forceinline__ void ldsm_x4(uint32_t r[4], uint32_t addr) {
    asm volatile("ldmatrix.sync.aligned.m8n8.x4.shared.b16 {%0,%1,%2,%3}, [%4];"
                 : "=r"(r[0]), "=r"(r[1]), "=r"(r[2]), "=r"(r[3]) : "r"(addr));
}

__device__ __forceinline__ void mma_f16(float c[4], const uint32_t a[4],
                                        uint32_t b0, uint32_t b1) {
    asm volatile(
        "mma.sync.aligned.m16n8k16.row.col.f32.f16.f16.f32 "
        "{%0,%1,%2,%3}, {%4,%5,%6,%7}, {%8,%9}, {%0,%1,%2,%3};"
        : "+f"(c[0]), "+f"(c[1]), "+f"(c[2]), "+f"(c[3])
        : "r"(a[0]), "r"(a[1]), "r"(a[2]), "r"(a[3]), "r"(b0), "r"(b1));
}

__device__ __forceinline__ void mbar_wait(uint32_t mbar, uint32_t parity) {
    asm volatile(
        "{\n\t.reg .pred P;\n\t"
        "W%=:\n\t"
        "mbarrier.try_wait.parity.acquire.cta.shared::cta.b64 P, [%0], %1, 0x989680;\n\t"
        "@!P bra W%=;\n\t"
        "}" :: "r"(mbar), "r"(parity) : "memory");
}

__device__ __forceinline__ void mbar_arrive(uint32_t mbar) {
    asm volatile("mbarrier.arrive.release.cta.shared::cta.b64 _, [%0];"
                 :: "r"(mbar) : "memory");
}

__device__ __forceinline__ float sigf(float v) { return 1.f / (1.f + __expf(-v)); }

__device__ __forceinline__ void sts_cvt16(uint32_t dst, float4 v0, float4 v1) {
    __half2 h[4];
    h[0] = __floats2half2_rn(v0.x, v0.y);
    h[1] = __floats2half2_rn(v0.z, v0.w);
    h[2] = __floats2half2_rn(v1.x, v1.y);
    h[3] = __floats2half2_rn(v1.z, v1.w);
    uint4 u = *(uint4*)h;
    asm volatile("st.shared.v4.b32 [%0], {%1,%2,%3,%4};"
                 :: "r"(dst), "r"(u.x), "r"(u.y), "r"(u.z), "r"(u.w));
}

// ---------------- fp16 GEMM + bias + sigmoid; 32x128 tile, decoupled mbarriers ----------------
// grid = (2, 256, 16); dead tiles exit immediately.
__global__ __launch_bounds__(THREADS, 3)
void gemm_kernel(const float* __restrict__ x,
                 const float* __restrict__ bias, float* __restrict__ out) {
    const int e = blockIdx.z;
    const int rows = g_counts[e];
    const int m_start = blockIdx.y * BM;
    if (m_start >= rows) return;
    const int n_start = blockIdx.x * BN;
    const int base = g_off[e];

    extern __shared__ char smem[];
    const uint32_t sb = smem_u32(smem);
    float* bsm = (float*)(smem + BIAS_OFF);
    int*   prm = (int*)(smem + PRM_OFF);

    const int t    = threadIdx.x;
    const int lane = t & 31;
    const int wid  = t >> 5;
    const int g    = lane >> 2;
    const int tig  = lane & 3;
    const int g2   = lane >> 3;
    const int lr   = lane & 7;
    const int warp_m = (wid & 1) * 16;    // 2 warps along M (16 rows)
    const int warp_n = (wid >> 1) * 32;   // 4 warps along N (32 cols)

    #define FULLB(s)  (sb + MBAR_OFF + (s) * 8)
    #define EMPTYB(s) (sb + MBAR_OFF + 32 + (s) * 8)

    if (t < BN) bsm[t] = bias[e * NO + n_start + t];
    if (t < BM) {
        int m = m_start + t;
        prm[t] = (m < rows) ? g_perm[base + m] : g_perm[base + m_start];
    }
    if (t == 0) {
        #pragma unroll
        for (int s = 0; s < STAGES; s++) {
            asm volatile("mbarrier.init.shared.b64 [%0], %1;"
                         :: "r"(FULLB(s)), "r"((uint32_t)THREADS) : "memory");
            asm volatile("mbarrier.init.shared.b64 [%0], %1;"
                         :: "r"(EMPTYB(s)), "r"((uint32_t)THREADS) : "memory");
        }
    }
    __syncthreads();

    // A staging: threads 0..127 -> row t>>2 (0..31), chunk t&3, swizzled dst
    const bool astage = (t < 128);
    const int arow = (t >> 2) & 31;
    const float* agp = x + (size_t)prm[arow] * NH + (t & 3) * 8;
    const uint32_t adst = (uint32_t)(arow * 64 + SWZ(arow, t & 3) * 16);
    // B bulk source: contiguous, pre-swizzled 8KB per slab
    const __half* bsrc = W16t + ((size_t)(e * 2 + blockIdx.x) * NSLAB) * (128 * 32);

    // ldmatrix row bases + swizzle keys
    uint32_t arb, asw, brb[2], bsw[2];
    const uint32_t cba = g2 >> 1;
    const uint32_t cbb = g2 & 1;
    {
        const int r = warp_m + (g2 & 1) * 8 + lr;
        arb = (uint32_t)(r * 64);
        asw = (uint32_t)((r >> 1) & 3);
    }
    #pragma unroll
    for (int p = 0; p < 2; p++) {
        const int r = warp_n + p * 16 + (g2 >> 1) * 8 + lr;
        brb[p] = (uint32_t)(r * 64);
        bsw[p] = (uint32_t)((r >> 1) & 3);
    }

    float acc[4][4];
    #pragma unroll
    for (int j = 0; j < 4; j++)
        #pragma unroll
        for (int q = 0; q < 4; q++) acc[j][q] = 0.f;

    // fill stage s with slab ks: STS(A, t<128) then arrive full (t0: expect_tx + B bulk)
    auto fill = [&](int ks, int s, float4 v0, float4 v1) {
        if (astage) sts_cvt16(sb + A_OFF + s * A_STAGE_B + adst, v0, v1);
        if (t == 0) {
            asm volatile("mbarrier.arrive.expect_tx.release.cta.shared::cta.b64 _, [%0], %1;"
                         :: "r"(FULLB(s)), "r"((uint32_t)B_STAGE_B) : "memory");
            asm volatile(
                "cp.async.bulk.shared::cluster.global.mbarrier::complete_tx::bytes "
                "[%0], [%1], %2, [%3];"
                :: "r"(sb + B_OFF + s * B_STAGE_B), "l"(bsrc + (size_t)ks * (128 * 32)),
                   "r"((uint32_t)B_STAGE_B), "r"(FULLB(s)) : "memory");
        } else {
            mbar_arrive(FULLB(s));
        }
    };

    // prologue: fill stages 0..2 (slabs 0..2)
    #pragma unroll
    for (int s = 0; s < STAGES - 1; s++) {
        float4 v0, v1;
        if (astage) {
            v0 = ((const float4*)(agp + s * BKS))[0];
            v1 = ((const float4*)(agp + s * BKS))[1];
        }
        fill(s, s, v0, v1);
    }
    // preload regs for slab 3 (staged at bottom of iteration 0)
    float4 p0, p1;
    if (astage) {
        p0 = ((const float4*)(agp + (STAGES - 1) * BKS))[0];
        p1 = ((const float4*)(agp + (STAGES - 1) * BKS))[1];
    }

    for (int ks = 0; ks < NSLAB; ks++) {
        const int s = ks & (STAGES - 1);
        mbar_wait(FULLB(s), (ks >> 2) & 1);

        // prefetch A LDG for slab ks+4 (consumed at bottom of NEXT iteration)
        float4 n0, n1;
        if (astage && ks + STAGES < NSLAB) {
            n0 = ((const float4*)(agp + (ks + STAGES) * BKS))[0];
            n1 = ((const float4*)(agp + (ks + STAGES) * BKS))[1];
        }

        const uint32_t ab = sb + A_OFF + s * A_STAGE_B;
        const uint32_t bb = sb + B_OFF + s * B_STAGE_B;
        #pragma unroll
        for (int kk = 0; kk < 2; kk++) {
            uint32_t a[4], b[2][4];
            ldsm_x4(a, ab + arb + (((cba | (kk << 1)) ^ asw) << 4));
            #pragma unroll
            for (int p = 0; p < 2; p++)
                ldsm_x4(b[p], bb + brb[p] + (((cbb | (kk << 1)) ^ bsw[p]) << 4));
            #pragma unroll
            for (int nf = 0; nf < 4; nf++)
                mma_f16(acc[nf], a, b[nf >> 1][(nf & 1) * 2],
                        b[nf >> 1][(nf & 1) * 2 + 1]);
        }
        mbar_arrive(EMPTYB(s));   // LDSM results in registers; stage s consumable

        // fill stage for slab ks+3 from regs loaded one full iteration ago
        const int ksn = ks + STAGES - 1;
        if (ksn < NSLAB) {
            const int sn = ksn & (STAGES - 1);
            if (ksn >= STAGES)
                mbar_wait(EMPTYB(sn), ((ksn - STAGES) >> 2) & 1);
            fill(ksn, sn, p0, p1);
        }
        p0 = n0;
        p1 = n1;
    }

    // epilogue: bias + sigmoid, scatter rows through prm
    #pragma unroll
    for (int h = 0; h < 2; h++) {
        const int rl = warp_m + g + h * 8;
        if (m_start + rl < rows) {
            const int orow = prm[rl];
            #pragma unroll
            for (int nf = 0; nf < 4; nf++) {
                const int col = warp_n + nf * 8 + 2 * tig;
                float v0 = acc[nf][h * 2 + 0] + bsm[col];
                float v1 = acc[nf][h * 2 + 1] + bsm[col + 1];
                float2 o;
                o.x = sigf(v0);
                o.y = sigf(v1);
                *(float2*)&out[(size_t)orow * NO + n_start + col] = o;
            }
        }
    }
}

extern "C" void kernel_launch(void* const* d_in, const int* in_sizes, int n_in,
                              void* d_out, int out_size) {
    const float* x    = (const float*)d_in[0];   // [B, H]
    const float* W    = (const float*)d_in[1];   // [E, O, H]
    const float* bias = (const float*)d_in[2];   // [E, O]
    const int*   num  = (const int*)d_in[3];     // [B]    int32
    const int*   c    = (const int*)d_in[4];     // [CMAP] int32
    float* out = (float*)d_out;                  // [B, O]

    const int cmap_n = in_sizes[4];

    cudaFuncSetAttribute(gemm_kernel, cudaFuncAttributeMaxDynamicSharedMemorySize,
                         SMEM_TOTAL);

    prep_kernel<<<2049, 256>>>(W, num, c, cmap_n);

    dim3 grid(NO / BN, NB / BM, NE);   // (2, 256, 16)
    gemm_kernel<<<grid, THREADS, SMEM_TOTAL>>>(x, bias, out);
}